// round 7
// baseline (speedup 1.0000x reference)
#include <cuda_runtime.h>
#include <cuda_bf16.h>

typedef unsigned long long u64;

#define Bb 8
#define Hh 32
#define Ff 8
#define Xx 128
#define Tt 256
#define Ts 255

// ---------------- device scratch ----------------
__device__ float  g_Gz0[Bb*Hh*Xx*Ff];                 // [b][c][x][f]
__device__ float  g_dD[(size_t)Bb*Hh*Ts*Xx];          // [b][c][t][x]
__device__ float4 g_W4[(size_t)Xx*Hh*16*Hh];          // [k][c][jp][i] = (wr0,wr1,wi0,wi1)
__device__ float2 g_dx[(size_t)Ts*Hh*Bb*Xx];          // [t][c][b][k]
__device__ float2 g_zinit[Xx*Hh*Bb];                  // [k][h][b]
__device__ float2 g_zall[(size_t)Bb*Hh*Tt*Xx];        // [bh][t][k]
__device__ float2 g_twf[127], g_twi[127];

// ---------------- f32x2 helpers ----------------
__device__ __forceinline__ u64 f2fma(u64 a,u64 b,u64 c){u64 d;asm("fma.rn.f32x2 %0,%1,%2,%3;":"=l"(d):"l"(a),"l"(b),"l"(c));return d;}
__device__ __forceinline__ void upk(u64 v,float&a,float&b){asm("mov.b64 {%0,%1},%2;":"=f"(a),"=f"(b):"l"(v));}

// ---------------- twiddles ----------------
__global__ void k_twiddle(){
    int t=threadIdx.x;
    if(t<127){
        int l=1<<(31-__clz(t+1)); int j=t+1-l;
        float s,c; sincospif((float)j/(float)l,&s,&c);
        g_twf[t]=make_float2(c,-s); g_twi[t]=make_float2(c,s);
    }
}

// ---------------- Stockham radix-2, 64 threads per FFT ----------------
__device__ __forceinline__ float2* do_fft(float2* x,float2* y,const float2* tw,int bt){
    float2 *s=x,*d=y;
    #pragma unroll
    for(int st=0;st<7;st++){
        int l=1<<st, j=bt&(l-1), q=bt>>st;
        float2 aa=s[q*l+j], bb=s[q*l+j+64], w=tw[l-1+j];
        float br=w.x*bb.x-w.y*bb.y, bi=w.x*bb.y+w.y*bb.x;
        d[q*2*l+j]=make_float2(aa.x+br,aa.y+bi);
        d[q*2*l+j+l]=make_float2(aa.x-br,aa.y-bi);
        __syncthreads();
        float2* tmp=s; s=d; d=tmp;
    }
    return s;
}

// ---------------- Gz0[b][c][x][f] = sum_h Gw[c][f][h] z0[b][h][x] ------------
__global__ void k_gz0(const float* __restrict__ z0,const float* __restrict__ Gw){
    __shared__ float z0s[Hh][Xx];
    int blk=blockIdx.x, c=blk&31, b=blk>>5, x=threadIdx.x;
    for(int e=x;e<Hh*Xx;e+=128) z0s[e>>7][e&127]=z0[(size_t)b*Hh*Xx+e];
    __syncthreads();
    #pragma unroll
    for(int f=0;f<Ff;f++){
        float acc=0.f;
        #pragma unroll 8
        for(int h=0;h<Hh;h++) acc+=Gw[(c*Ff+f)*Hh+h]*z0s[h][x];
        g_Gz0[((size_t)blk*Xx+x)*Ff+f]=acc;
    }
}

// ---------------- W transpose via smem tiles ----------------
__global__ void k_wt(const float* __restrict__ Wr,const float* __restrict__ Wi){
    __shared__ float sr[32][33], si[32][33];
    int blk=blockIdx.x, c=blk&31, kk=blk>>5, tid=threadIdx.x;
    for(int e=tid;e<1024;e+=256){
        int i=e>>5, j=e&31;
        size_t s=(((size_t)kk*Hh+i)*Hh+c)*Hh+j;
        sr[i][j]=Wr[s]; si[i][j]=Wi[s];
    }
    __syncthreads();
    for(int e=tid;e<512;e+=256){
        int i=e&31, jp=e>>5;
        g_W4[((size_t)blk*16+jp)*32+i]=
            make_float4(sr[i][2*jp],sr[i][2*jp+1],si[i][2*jp],si[i][2*jp+1]);
    }
}

// ---------------- dD[b][c][t][x] = sum_f Gz0*(xi[t+1]-xi[t]) ----------------
__global__ void k_dD(const float* __restrict__ xi){
    __shared__ float gs[32][8];
    __shared__ float tr[32][257];
    int blk=blockIdx.x;                // (b*32+c)*4 + xq
    int xq=blk&3, bc=blk>>2, b=bc>>5, tid=threadIdx.x;
    for(int e=tid;e<256;e+=256) gs[e>>3][e&7]=g_Gz0[((size_t)bc*Xx+xq*32)*Ff+e];
    __syncthreads();
    int t=tid;
    #pragma unroll 1
    for(int xs=0;xs<32;xs++){
        float acc=0.f;
        if(t<Ts){
            int x=xq*32+xs;
            #pragma unroll
            for(int f=0;f<Ff;f++){
                const float* p=xi+(((size_t)(b*Ff+f)*Xx)+x)*Tt+t;
                acc+=gs[xs][f]*(p[1]-p[0]);
            }
        }
        tr[xs][t]=acc;
    }
    __syncthreads();
    for(int e=tid;e<Ts*32;e+=256){
        int xs=e&31, tt=e>>5;
        g_dD[((size_t)bc*Ts+tt)*Xx+xq*32+xs]=tr[xs][tt];
    }
}

// ---------------- FFT of dD rows -> g_dx[t][c][b][k] ----------------
__global__ void k_fft_dx(){
    __shared__ float2 xb[4][128], yb[4][128], tws[127];
    int tid=threadIdx.x;
    for(int q=tid;q<127;q+=256) tws[q]=g_twf[q];
    int blk=blockIdx.x, tc=blk&63, bc=blk>>6, c=bc&31, b=bc>>5;
    for(int e=tid;e<512;e+=256){
        int sub=e>>7, xx=e&127, t=tc*4+sub;
        float v=(t<Ts)? g_dD[((size_t)bc*Ts+t)*Xx+xx] : 0.f;
        if(xx&1) v=-v;                              // fftshift
        xb[sub][xx]=make_float2(v,0.f);
    }
    __syncthreads();
    int sub=tid>>6, bt=tid&63;
    float2* r=do_fft(xb[sub],yb[sub],tws,bt);
    int t=tc*4+sub;
    if(t<Ts){
        size_t base=((size_t)t*256 + c*8 + b)*Xx;
        g_dx[base+bt]=r[bt];
        g_dx[base+bt+64]=r[bt+64];
    }
}

// ---------------- FFT of z0 -> g_zinit[k][h][b] ----------------
__global__ void k_fft_z0(const float* __restrict__ z0){
    __shared__ float2 xb[4][128], yb[4][128], tws[127];
    int tid=threadIdx.x;
    for(int q=tid;q<127;q+=256) tws[q]=g_twf[q];
    int blk=blockIdx.x, hc=blk&7, b=blk>>3;
    for(int e=tid;e<512;e+=256){
        int sub=e>>7, xx=e&127, h=hc*4+sub;
        float v=z0[((size_t)b*Hh+h)*Xx+xx];
        if(xx&1) v=-v;
        xb[sub][xx]=make_float2(v,0.f);
    }
    __syncthreads();
    int sub=tid>>6, bt=tid&63, h=hc*4+sub;
    float2* r=do_fft(xb[sub],yb[sub],tws,bt);
    g_zinit[((size_t)bt*Hh+h)*Bb+b]=r[bt];
    g_zinit[((size_t)(bt+64)*Hh+h)*Bb+b]=r[bt+64];
}

// ---------------- sequential CDE scan (v2): 512 threads, Y-outer-product ----
// Y[b][c][j] = dx[b][c]*z[b][j] built in smem each step; main loop is
// s[i] = sum_{cj} W[cj][i]*Y[cj]: per (pair,b): 1 broadcast LDS.128 + 4 fma.f32x2.
#define YSTR 513
#define OFF_PART (Bb*YSTR*16)            /* bytes offset of part = 8*513*16 = 65664 */
#define OFF_ZRE  (OFF_PART + 16*Bb*Hh*8) /* + 32768 = 98432 */
#define OFF_ZIM  (OFF_ZRE + Bb*33*4 + 32)
#define SMEM_SZ  (OFF_ZIM + Bb*33*4 + 32)

__global__ void __launch_bounds__(512,1) k_scan(){
    extern __shared__ char smraw[];
    float4* Y4   = (float4*)smraw;                    // [b][pair] stride YSTR
    float2* part = (float2*)(smraw + OFF_PART);       // [w][b][i]
    float*  zre  = (float*) (smraw + OFF_ZRE);        // [b][j] stride 33
    float*  zim  = (float*) (smraw + OFF_ZIM);
    int tid=threadIdx.x, k=blockIdx.x;
    int w=tid>>5, lane=tid&31;
    int cB=tid>>4, rB=tid&15, bB=rB>>1, jh=rB&1;      // Y-build mapping
    int iR=tid&31, bR=tid>>5;                         // reduce mapping (tid<256)

    if(tid<256){
        float2 v=g_zinit[(size_t)k*256 + iR*8 + bR];
        zre[bR*33+iR]=v.x; zim[bR*33+iR]=v.y;
        g_zall[((size_t)(bR*Hh+iR)*Tt)*Xx+k]=v;
    }
    float2 vdx=g_dx[((size_t)0*256 + cB*8 + bB)*Xx + k];
    const float4* Wp = g_W4 + (size_t)k*16384 + (size_t)(w*32)*32 + lane;
    const float4* Yb = Y4 + w*32;

    #pragma unroll 1
    for(int t=0;t<Ts;t++){
        __syncthreads();                              // z update visible; Y free
        // ---- build Y ----
        {
            float dxr=vdx.x, dxi=vdx.y;
            #pragma unroll
            for(int q=0;q<8;q++){
                int j=jh*16+2*q;
                float zr0=zre[bB*33+j],   zi0=zim[bB*33+j];
                float zr1=zre[bB*33+j+1], zi1=zim[bB*33+j+1];
                float yr0=dxr*zr0-dxi*zi0, yi0=dxr*zi0+dxi*zr0;
                float yr1=dxr*zr1-dxi*zi1, yi1=dxr*zi1+dxi*zr1;
                Y4[bB*YSTR + cB*16 + jh*8 + q]=make_float4(yr0,yr1,yi0,yi1);
            }
        }
        if(t+1<Ts) vdx=g_dx[((size_t)(t+1)*256 + cB*8 + bB)*Xx + k];
        __syncthreads();                              // Y ready
        // ---- main dot ----
        u64 aRe[8],aIm[8];
        #pragma unroll
        for(int b=0;b<8;b++){aRe[b]=0ULL;aIm[b]=0ULL;}
        #pragma unroll 1
        for(int p=0;p<32;p++){
            float4 wv=__ldg(Wp+p*32);
            u64 wr=*(const u64*)&wv.x, wi=*(const u64*)&wv.z;
            u64 win=wi^0x8000000080000000ULL;
            #pragma unroll
            for(int b=0;b<8;b++){
                float4 y=Yb[b*YSTR+p];
                u64 yr=*(const u64*)&y.x, yi=*(const u64*)&y.z;
                aRe[b]=f2fma(wr,yr,aRe[b]); aRe[b]=f2fma(win,yi,aRe[b]);
                aIm[b]=f2fma(wr,yi,aIm[b]); aIm[b]=f2fma(wi,yr,aIm[b]);
            }
        }
        #pragma unroll
        for(int b=0;b<8;b++){
            float r0,r1,s0,s1;
            upk(aRe[b],r0,r1); upk(aIm[b],s0,s1);
            part[(w*8+b)*32+lane]=make_float2(r0+r1,s0+s1);
        }
        __syncthreads();                              // partials ready
        if(tid<256){
            float sr=0.f,si=0.f;
            #pragma unroll
            for(int g=0;g<16;g++){
                float2 pv=part[(g*8+bR)*32+iR];
                sr+=pv.x; si+=pv.y;
            }
            float nr=zre[bR*33+iR]+sr, ni=zim[bR*33+iR]+si;
            zre[bR*33+iR]=nr; zim[bR*33+iR]=ni;
            g_zall[((size_t)(bR*Hh+iR)*Tt+(t+1))*Xx+k]=make_float2(nr,ni);
        }
    }
}

// ---------------- inverse FFT, 32 t per block, smem transpose ---------------
__global__ void k_fft_out(float* __restrict__ out){
    __shared__ float2 xb[4][128], yb[4][128], tws[127];
    __shared__ float tr[128][33];
    int tid=threadIdx.x;
    for(int q=tid;q<127;q+=256) tws[q]=g_twi[q];
    int blk=blockIdx.x, tg=blk&7, bh=blk>>3;
    int sub=tid>>6, bt=tid&63;
    #pragma unroll 1
    for(int rr8=0;rr8<8;rr8++){
        int t0=tg*32+rr8*4;
        __syncthreads();
        for(int e=tid;e<512;e+=256){
            int su=e>>7, kk=e&127;
            xb[su][kk]=g_zall[((size_t)bh*Tt+t0+su)*Xx+kk];
        }
        __syncthreads();
        float2* r=do_fft(xb[sub],yb[sub],tws,bt);
        int tt=rr8*4+sub;
        tr[bt][tt]=r[bt].x;
        tr[bt+64][tt]=r[bt+64].x;
    }
    __syncthreads();
    const float sc=1.f/128.f;
    for(int e=tid;e<4096;e+=256){
        int ttt=e&31, x=e>>5;
        float s=(x&1)? -sc:sc;                      // ifftshift sign
        out[((size_t)bh*Xx+x)*Tt+tg*32+ttt]=tr[x][ttt]*s;
    }
}

// ---------------- launch ----------------
extern "C" void kernel_launch(void* const* d_in,const int* in_sizes,int n_in,
                              void* d_out,int out_size){
    const float* z0=(const float*)d_in[0];
    const float* xi=(const float*)d_in[1];
    // d_in[2] = A : algebraically dead (cancels in dX)
    const float* Gw=(const float*)d_in[3];
    const float* Wr=(const float*)d_in[4];
    const float* Wi=(const float*)d_in[5];
    float* out=(float*)d_out;

    cudaFuncSetAttribute(k_scan, cudaFuncAttributeMaxDynamicSharedMemorySize, SMEM_SZ);

    k_twiddle<<<1,128>>>();
    k_gz0<<<Bb*Hh,128>>>(z0,Gw);
    k_wt<<<Xx*Hh,256>>>(Wr,Wi);
    k_dD<<<Bb*Hh*4,256>>>(xi);
    k_fft_z0<<<Bb*8,256>>>(z0);
    k_fft_dx<<<Bb*Hh*64,256>>>();
    k_scan<<<Xx,512,SMEM_SZ>>>();
    k_fft_out<<<Bb*Hh*8,256>>>(out);
}

// round 9
// speedup vs baseline: 1.4593x; 1.4593x over previous
#include <cuda_runtime.h>
#include <cuda_bf16.h>

typedef unsigned long long u64;

#define Bb 8
#define Hh 32
#define Ff 8
#define Xx 128
#define Tt 256
#define Ts 255

// ---------------- device scratch ----------------
__device__ float  g_Gz0[Bb*Hh*Xx*Ff];                 // [b][c][x][f]
__device__ float  g_dD[(size_t)Bb*Hh*Ts*Xx];          // [b][c][t][x]
__device__ float4 g_W4[(size_t)Xx*Hh*16*Hh];          // [k][c][jp][i] = (wr0,wr1,wi0,wi1)
__device__ float2 g_dx[(size_t)Ts*Hh*Bb*Xx];          // [t][c][b][k]
__device__ float2 g_zinit[Xx*Hh*Bb];                  // [k][h][b]
__device__ float2 g_zall[(size_t)Bb*Hh*Tt*Xx];        // [bh][t][k]
__device__ float2 g_twf[127], g_twi[127];

// ---------------- f32x2 helpers ----------------
__device__ __forceinline__ u64 f2fma(u64 a,u64 b,u64 c){u64 d;asm("fma.rn.f32x2 %0,%1,%2,%3;":"=l"(d):"l"(a),"l"(b),"l"(c));return d;}
__device__ __forceinline__ u64 f2add(u64 a,u64 b){u64 d;asm("add.rn.f32x2 %0,%1,%2;":"=l"(d):"l"(a),"l"(b));return d;}
__device__ __forceinline__ u64 pkd(float a){u64 d;asm("mov.b64 %0,{%1,%1};":"=l"(d):"f"(a));return d;}
__device__ __forceinline__ void upk(u64 v,float&a,float&b){asm("mov.b64 {%0,%1},%2;":"=f"(a),"=f"(b):"l"(v));}

// ---------------- twiddles ----------------
__global__ void k_twiddle(){
    int t=threadIdx.x;
    if(t<127){
        int l=1<<(31-__clz(t+1)); int j=t+1-l;
        float s,c; sincospif((float)j/(float)l,&s,&c);
        g_twf[t]=make_float2(c,-s); g_twi[t]=make_float2(c,s);
    }
}

// ---------------- Stockham radix-2, 64 threads per FFT ----------------
__device__ __forceinline__ float2* do_fft(float2* x,float2* y,const float2* tw,int bt){
    float2 *s=x,*d=y;
    #pragma unroll
    for(int st=0;st<7;st++){
        int l=1<<st, j=bt&(l-1), q=bt>>st;
        float2 aa=s[q*l+j], bb=s[q*l+j+64], w=tw[l-1+j];
        float br=w.x*bb.x-w.y*bb.y, bi=w.x*bb.y+w.y*bb.x;
        d[q*2*l+j]=make_float2(aa.x+br,aa.y+bi);
        d[q*2*l+j+l]=make_float2(aa.x-br,aa.y-bi);
        __syncthreads();
        float2* tmp=s; s=d; d=tmp;
    }
    return s;
}

// ---------------- Gz0[b][c][x][f] = sum_h Gw[c][f][h] z0[b][h][x] ------------
__global__ void k_gz0(const float* __restrict__ z0,const float* __restrict__ Gw){
    __shared__ float z0s[Hh][Xx];
    int blk=blockIdx.x, c=blk&31, b=blk>>5, x=threadIdx.x;
    for(int e=x;e<Hh*Xx;e+=128) z0s[e>>7][e&127]=z0[(size_t)b*Hh*Xx+e];
    __syncthreads();
    #pragma unroll
    for(int f=0;f<Ff;f++){
        float acc=0.f;
        #pragma unroll 8
        for(int h=0;h<Hh;h++) acc+=Gw[(c*Ff+f)*Hh+h]*z0s[h][x];
        g_Gz0[((size_t)blk*Xx+x)*Ff+f]=acc;
    }
}

// ---------------- W transpose via smem tiles ----------------
__global__ void k_wt(const float* __restrict__ Wr,const float* __restrict__ Wi){
    __shared__ float sr[32][33], si[32][33];
    int blk=blockIdx.x, c=blk&31, kk=blk>>5, tid=threadIdx.x;
    for(int e=tid;e<1024;e+=256){
        int i=e>>5, j=e&31;
        size_t s=(((size_t)kk*Hh+i)*Hh+c)*Hh+j;
        sr[i][j]=Wr[s]; si[i][j]=Wi[s];
    }
    __syncthreads();
    for(int e=tid;e<512;e+=256){
        int i=e&31, jp=e>>5;
        g_W4[((size_t)blk*16+jp)*32+i]=
            make_float4(sr[i][2*jp],sr[i][2*jp+1],si[i][2*jp],si[i][2*jp+1]);
    }
}

// ---------------- dD[b][c][t][x] = sum_f Gz0*(xi[t+1]-xi[t]) ----------------
__global__ void k_dD(const float* __restrict__ xi){
    __shared__ float gs[32][8];
    __shared__ float tr[32][257];
    int blk=blockIdx.x;                // (b*32+c)*4 + xq
    int xq=blk&3, bc=blk>>2, b=bc>>5, tid=threadIdx.x;
    for(int e=tid;e<256;e+=256) gs[e>>3][e&7]=g_Gz0[((size_t)bc*Xx+xq*32)*Ff+e];
    __syncthreads();
    int t=tid;
    #pragma unroll 1
    for(int xs=0;xs<32;xs++){
        float acc=0.f;
        if(t<Ts){
            int x=xq*32+xs;
            #pragma unroll
            for(int f=0;f<Ff;f++){
                const float* p=xi+(((size_t)(b*Ff+f)*Xx)+x)*Tt+t;
                acc+=gs[xs][f]*(p[1]-p[0]);
            }
        }
        tr[xs][t]=acc;
    }
    __syncthreads();
    for(int e=tid;e<Ts*32;e+=256){
        int xs=e&31, tt=e>>5;
        g_dD[((size_t)bc*Ts+tt)*Xx+xq*32+xs]=tr[xs][tt];
    }
}

// ---------------- FFT of dD rows -> g_dx[t][c][b][k] ----------------
__global__ void k_fft_dx(){
    __shared__ float2 xb[4][128], yb[4][128], tws[127];
    int tid=threadIdx.x;
    for(int q=tid;q<127;q+=256) tws[q]=g_twf[q];
    int blk=blockIdx.x, tc=blk&63, bc=blk>>6, c=bc&31, b=bc>>5;
    for(int e=tid;e<512;e+=256){
        int sub=e>>7, xx=e&127, t=tc*4+sub;
        float v=(t<Ts)? g_dD[((size_t)bc*Ts+t)*Xx+xx] : 0.f;
        if(xx&1) v=-v;                              // fftshift
        xb[sub][xx]=make_float2(v,0.f);
    }
    __syncthreads();
    int sub=tid>>6, bt=tid&63;
    float2* r=do_fft(xb[sub],yb[sub],tws,bt);
    int t=tc*4+sub;
    if(t<Ts){
        size_t base=((size_t)t*256 + c*8 + b)*Xx;
        g_dx[base+bt]=r[bt];
        g_dx[base+bt+64]=r[bt+64];
    }
}

// ---------------- FFT of z0 -> g_zinit[k][h][b] ----------------
__global__ void k_fft_z0(const float* __restrict__ z0){
    __shared__ float2 xb[4][128], yb[4][128], tws[127];
    int tid=threadIdx.x;
    for(int q=tid;q<127;q+=256) tws[q]=g_twf[q];
    int blk=blockIdx.x, hc=blk&7, b=blk>>3;
    for(int e=tid;e<512;e+=256){
        int sub=e>>7, xx=e&127, h=hc*4+sub;
        float v=z0[((size_t)b*Hh+h)*Xx+xx];
        if(xx&1) v=-v;
        xb[sub][xx]=make_float2(v,0.f);
    }
    __syncthreads();
    int sub=tid>>6, bt=tid&63, h=hc*4+sub;
    float2* r=do_fft(xb[sub],yb[sub],tws,bt);
    g_zinit[((size_t)bt*Hh+h)*Bb+b]=r[bt];
    g_zinit[((size_t)(bt+64)*Hh+h)*Bb+b]=r[bt+64];
}

// ---------------- sequential CDE scan (v3): register-M + 3M complex ---------
// Per step: build M_t[b,i,j] = sum_c dx[b,c] W[c,i,j] into registers (no z
// dependence -> off the serial path), then apply M_t z_t (tiny serial part).
// 3M trick: P1=sum wr*dxr, P2=sum wi*dxi, P3=sum (wr+wi)(dxr+dxi);
// Mre=P1-P2, Mim=P3-P1-P2.  Thread (w=tid>>5, i=lane) owns j=4w..4w+3,
// f32x2-packed over j-pairs (natural u64 aliases of W float4 halves).
#define SGN64 0x8000000080000000ULL
__global__ void __launch_bounds__(256,1) k_scan(){
    __shared__ __align__(16) float zre[Bb*34], zim[Bb*34];
    __shared__ u64 dre_u[2][256], dim_u[2][256], dsm_u[2][256];
    __shared__ float2 part[8*256];
    int tid=threadIdx.x, k=blockIdx.x;
    int w=tid>>5, lane=tid&31;
    int bR=tid>>5, iR=tid&31;

    {   float2 v=g_zinit[(size_t)k*256 + iR*8 + bR];
        zre[bR*34+iR]=v.x; zim[bR*34+iR]=v.y;
        g_zall[((size_t)(bR*Hh+iR)*Tt)*Xx+k]=v;
        float2 d0=g_dx[(size_t)tid*Xx+k];           // stage dx for t=0
        dre_u[0][tid]=pkd(d0.x); dim_u[0][tid]=pkd(d0.y); dsm_u[0][tid]=pkd(d0.x+d0.y);
    }
    size_t wbase=(size_t)k*16384 + (size_t)(2*w)*32 + lane;
    u64 m1=pkd(-1.f);

    #pragma unroll 1
    for(int t=0;t<Ts;t++){
        __syncthreads();                            // z_t + dx buf ready
        float2 vdx;
        if(t+1<Ts) vdx=g_dx[((size_t)(t+1)*256+tid)*Xx+k];
        int pb=t&1;
        u64 P1[2][8],P2[2][8],P3[2][8];
        #pragma unroll
        for(int jp=0;jp<2;jp++)
            #pragma unroll
            for(int b=0;b<8;b++){P1[jp][b]=0ULL;P2[jp][b]=0ULL;P3[jp][b]=0ULL;}
        // ---- build M_t (independent of z; fills the step) ----
        #pragma unroll 2
        for(int c=0;c<32;c++){
            float4 wv0=__ldg(&g_W4[wbase + (size_t)c*512]);
            float4 wv1=__ldg(&g_W4[wbase + (size_t)c*512 + 32]);
            u64 wr0=*(const u64*)&wv0.x, wi0=*(const u64*)&wv0.z, ws0=f2add(wr0,wi0);
            u64 wr1=*(const u64*)&wv1.x, wi1=*(const u64*)&wv1.z, ws1=f2add(wr1,wi1);
            const u64* dre=&dre_u[pb][c*8];
            const u64* dim=&dim_u[pb][c*8];
            const u64* dsm=&dsm_u[pb][c*8];
            #pragma unroll
            for(int b=0;b<8;b++){
                u64 xr=dre[b], xi=dim[b], xs=dsm[b];
                P1[0][b]=f2fma(wr0,xr,P1[0][b]); P1[1][b]=f2fma(wr1,xr,P1[1][b]);
                P2[0][b]=f2fma(wi0,xi,P2[0][b]); P2[1][b]=f2fma(wi1,xi,P2[1][b]);
                P3[0][b]=f2fma(ws0,xs,P3[0][b]); P3[1][b]=f2fma(ws1,xs,P3[1][b]);
            }
        }
        // ---- apply M_t to z_t ----
        #pragma unroll
        for(int b=0;b<8;b++){
            u64 accR=0ULL, accI=0ULL;
            #pragma unroll
            for(int jp=0;jp<2;jp++){
                u64 mre=f2fma(P2[jp][b],m1,P1[jp][b]);
                u64 mim=f2fma(P1[jp][b],m1,P3[jp][b]);
                mim=f2fma(P2[jp][b],m1,mim);
                u64 zr=*(const u64*)&zre[b*34 + 4*w + 2*jp];
                u64 zi=*(const u64*)&zim[b*34 + 4*w + 2*jp];
                accR=f2fma(mre,zr,accR); accR=f2fma(mim^SGN64,zi,accR);
                accI=f2fma(mre,zi,accI); accI=f2fma(mim,zr,accI);
            }
            float r0,r1,s0,s1;
            upk(accR,r0,r1); upk(accI,s0,s1);
            part[w*256 + b*32 + lane]=make_float2(r0+r1,s0+s1);
        }
        if(t+1<Ts){                                  // stage dx for t+1
            int nb=pb^1;
            dre_u[nb][tid]=pkd(vdx.x); dim_u[nb][tid]=pkd(vdx.y); dsm_u[nb][tid]=pkd(vdx.x+vdx.y);
        }
        __syncthreads();                            // partials + staging done
        // ---- reduce over the 8 j-groups, update z ----
        float sr=0.f,si=0.f;
        #pragma unroll
        for(int g=0;g<8;g++){
            float2 p=part[g*256 + bR*32 + iR];
            sr+=p.x; si+=p.y;
        }
        float nr=zre[bR*34+iR]+sr, ni=zim[bR*34+iR]+si;
        zre[bR*34+iR]=nr; zim[bR*34+iR]=ni;
        g_zall[((size_t)(bR*Hh+iR)*Tt+(t+1))*Xx+k]=make_float2(nr,ni);
    }
}

// ---------------- inverse FFT, 32 t per block, smem transpose ---------------
__global__ void k_fft_out(float* __restrict__ out){
    __shared__ float2 xb[4][128], yb[4][128], tws[127];
    __shared__ float tr[128][33];
    int tid=threadIdx.x;
    for(int q=tid;q<127;q+=256) tws[q]=g_twi[q];
    int blk=blockIdx.x, tg=blk&7, bh=blk>>3;
    int sub=tid>>6, bt=tid&63;
    #pragma unroll 1
    for(int rr8=0;rr8<8;rr8++){
        int t0=tg*32+rr8*4;
        __syncthreads();
        for(int e=tid;e<512;e+=256){
            int su=e>>7, kk=e&127;
            xb[su][kk]=g_zall[((size_t)bh*Tt+t0+su)*Xx+kk];
        }
        __syncthreads();
        float2* r=do_fft(xb[sub],yb[sub],tws,bt);
        int tt=rr8*4+sub;
        tr[bt][tt]=r[bt].x;
        tr[bt+64][tt]=r[bt+64].x;
    }
    __syncthreads();
    const float sc=1.f/128.f;
    for(int e=tid;e<4096;e+=256){
        int ttt=e&31, x=e>>5;
        float s=(x&1)? -sc:sc;                      // ifftshift sign
        out[((size_t)bh*Xx+x)*Tt+tg*32+ttt]=tr[x][ttt]*s;
    }
}

// ---------------- launch ----------------
extern "C" void kernel_launch(void* const* d_in,const int* in_sizes,int n_in,
                              void* d_out,int out_size){
    const float* z0=(const float*)d_in[0];
    const float* xi=(const float*)d_in[1];
    // d_in[2] = A : algebraically dead (cancels in dX)
    const float* Gw=(const float*)d_in[3];
    const float* Wr=(const float*)d_in[4];
    const float* Wi=(const float*)d_in[5];
    float* out=(float*)d_out;

    k_twiddle<<<1,128>>>();
    k_gz0<<<Bb*Hh,128>>>(z0,Gw);
    k_wt<<<Xx*Hh,256>>>(Wr,Wi);
    k_dD<<<Bb*Hh*4,256>>>(xi);
    k_fft_z0<<<Bb*8,256>>>(z0);
    k_fft_dx<<<Bb*Hh*64,256>>>();
    k_scan<<<Xx,256>>>();
    k_fft_out<<<Bb*Hh*8,256>>>(out);
}